// round 11
// baseline (speedup 1.0000x reference)
#include <cuda_runtime.h>
#include <math.h>

#define B_TOTAL 65536
#define OBS 64
#define ACTD 16
#define IND 145
#define HID 256
#define FEAT 128
#define NENV 64
#define EMB 32
#define ROWS 32
#define NTHREADS 256

typedef unsigned long long u64;

__device__ __forceinline__ u64 fma2(u64 a, u64 b, u64 c) {
    u64 d; asm("fma.rn.f32x2 %0,%1,%2,%3;" : "=l"(d) : "l"(a), "l"(b), "l"(c)); return d;
}
__device__ __forceinline__ u64 pack2(float x, float y) {
    u64 d; asm("mov.b64 %0,{%1,%2};" : "=l"(d) : "f"(x), "f"(y)); return d;
}
__device__ __forceinline__ void unpack2(u64 v, float& x, float& y) {
    asm("mov.b64 {%0,%1},%2;" : "=f"(x), "=f"(y) : "l"(v));
}

// ---- shared memory layout (float offsets), all bases 16B-aligned ----
// transposed activation tiles T[k][row], stride 34 (32 rows + 2 pad, even for u64 pairs)
#define TS 34
#define OFF_XT    0                 // 145*34 = 4930 -> region A = 4932
#define OFF_FEAT  0                 // feat row-major 32*132 = 4224, aliases A
#define FEAT_STRIDE 132
#define OFF_H0T   4932              // 256*34 = 8704
#define OFF_H1T   13636             // 256*34 = 8704
#define OFF_EEMB  22340             // 64*32 = 2048
#define OFF_COEF  24388             // 64
#define SMEM_FLOATS 24452           // 97808 bytes -> 2 CTAs/SM

// Transposed dense layer with packed f32x2 FMA (output transposed).
// tx = tid&63 -> cols {tx+64j}, ty = tid>>6 (0..3) -> rows [ty*8, ty*8+8) as 4 pairs
template<int NJ>
__device__ __forceinline__ void dense_layerT(
    const float* __restrict__ inT, int K,
    const float* __restrict__ W, const float* __restrict__ bias, int C,
    float* __restrict__ outT, int tid)
{
    const int tx = tid & 63;
    const int ty = tid >> 6;
    u64 acc[4][NJ];
#pragma unroll
    for (int j = 0; j < NJ; j++) {
        float bb = __ldg(&bias[tx + 64 * j]);
        u64 b2 = pack2(bb, bb);
#pragma unroll
        for (int p = 0; p < 4; p++) acc[p][j] = b2;
    }
    const float* ip = inT + ty * 8;
#pragma unroll 4
    for (int k = 0; k < K; k++) {
        u64 wv[NJ];
#pragma unroll
        for (int j = 0; j < NJ; j++) {
            float w = __ldg(&W[(size_t)k * C + tx + 64 * j]);
            wv[j] = pack2(w, w);
        }
        const float* col = ip + k * TS;
        u64 x0 = *(const u64*)(col + 0);
        u64 x1 = *(const u64*)(col + 2);
        u64 x2 = *(const u64*)(col + 4);
        u64 x3 = *(const u64*)(col + 6);
#pragma unroll
        for (int j = 0; j < NJ; j++) {
            acc[0][j] = fma2(x0, wv[j], acc[0][j]);
            acc[1][j] = fma2(x1, wv[j], acc[1][j]);
            acc[2][j] = fma2(x2, wv[j], acc[2][j]);
            acc[3][j] = fma2(x3, wv[j], acc[3][j]);
        }
    }
#pragma unroll
    for (int p = 0; p < 4; p++) {
#pragma unroll
        for (int j = 0; j < NJ; j++) {
            float a, b; unpack2(acc[p][j], a, b);
            int c = tx + 64 * j;
            outT[c * TS + ty * 8 + 2 * p]     = fmaxf(a, 0.01f * a);
            outT[c * TS + ty * 8 + 2 * p + 1] = fmaxf(b, 0.01f * b);
        }
    }
}

// Same compute, but stores ROW-MAJOR output (for the projection phase).
template<int NJ>
__device__ __forceinline__ void dense_layer_rm(
    const float* __restrict__ inT, int K,
    const float* __restrict__ W, const float* __restrict__ bias, int C,
    float* __restrict__ out_rm, int out_stride, int tid)
{
    const int tx = tid & 63;
    const int ty = tid >> 6;
    u64 acc[4][NJ];
#pragma unroll
    for (int j = 0; j < NJ; j++) {
        float bb = __ldg(&bias[tx + 64 * j]);
        u64 b2 = pack2(bb, bb);
#pragma unroll
        for (int p = 0; p < 4; p++) acc[p][j] = b2;
    }
    const float* ip = inT + ty * 8;
#pragma unroll 4
    for (int k = 0; k < K; k++) {
        u64 wv[NJ];
#pragma unroll
        for (int j = 0; j < NJ; j++) {
            float w = __ldg(&W[(size_t)k * C + tx + 64 * j]);
            wv[j] = pack2(w, w);
        }
        const float* col = ip + k * TS;
        u64 x0 = *(const u64*)(col + 0);
        u64 x1 = *(const u64*)(col + 2);
        u64 x2 = *(const u64*)(col + 4);
        u64 x3 = *(const u64*)(col + 6);
#pragma unroll
        for (int j = 0; j < NJ; j++) {
            acc[0][j] = fma2(x0, wv[j], acc[0][j]);
            acc[1][j] = fma2(x1, wv[j], acc[1][j]);
            acc[2][j] = fma2(x2, wv[j], acc[2][j]);
            acc[3][j] = fma2(x3, wv[j], acc[3][j]);
        }
    }
#pragma unroll
    for (int p = 0; p < 4; p++) {
#pragma unroll
        for (int j = 0; j < NJ; j++) {
            float a, b; unpack2(acc[p][j], a, b);
            int c = tx + 64 * j;
            int r = ty * 8 + 2 * p;
            out_rm[r * out_stride + c]       = fmaxf(a, 0.01f * a);
            out_rm[(r + 1) * out_stride + c] = fmaxf(b, 0.01f * b);
        }
    }
}

extern __shared__ float sm[];

__global__ void __launch_bounds__(NTHREADS, 2)
udp_encoder_kernel(
    const float* __restrict__ obs,  const float* __restrict__ act,
    const float* __restrict__ obs2, const float* __restrict__ rew,
    const float* __restrict__ W0,   const float* __restrict__ b0,
    const float* __restrict__ W1,   const float* __restrict__ b1,
    const float* __restrict__ W2,   const float* __restrict__ b2,
    const float* __restrict__ Wp,   const float* __restrict__ ee,
    const float* __restrict__ sig,  float* __restrict__ out)
{
    const int tid = threadIdx.x;
    const size_t row0 = (size_t)blockIdx.x * ROWS;

    // ---- stage e_emb + sigma coefficients ----
    for (int i = tid; i < NENV * EMB; i += NTHREADS) sm[OFF_EEMB + i] = ee[i];
    if (tid < NENV) {
        float s = sig[tid];
        sm[OFF_COEF + tid] = -1.0f / (64.0f * s * s);
    }

    // ---- build transposed input tile xT[k][row] ----
    for (int i = tid; i < ROWS * OBS; i += NTHREADS) {
        int r = i >> 6, k = i & 63;
        float o  = obs [(row0 + r) * OBS + k];
        float o2 = obs2[(row0 + r) * OBS + k];
        sm[OFF_XT + k * TS + r]        = o;
        sm[OFF_XT + (64 + k) * TS + r] = o2 - o;
    }
    for (int i = tid; i < ROWS * ACTD; i += NTHREADS) {
        int r = i >> 4, k = i & 15;
        sm[OFF_XT + (128 + k) * TS + r] = act[(row0 + r) * ACTD + k];
    }
    if (tid < ROWS) sm[OFF_XT + 144 * TS + tid] = rew[row0 + tid];
    __syncthreads();

    // ---- MLP ----
    dense_layerT<4>(sm + OFF_XT,  IND, W0, b0, HID, sm + OFF_H0T, tid);
    __syncthreads();
    dense_layerT<4>(sm + OFF_H0T, HID, W1, b1, HID, sm + OFF_H1T, tid);
    __syncthreads();
    dense_layer_rm<2>(sm + OFF_H1T, HID, W2, b2, FEAT, sm + OFF_FEAT, FEAT_STRIDE, tid);
    __syncthreads();

    // ==== projection + distance + argmin: barrier-free, per-warp rows ====
    const int lane = tid & 31;
    const int wrp  = tid >> 5;          // 8 warps x 4 rows
    const int nl   = lane >> 3;         // env within group (0..3)
    const int eb   = lane & 7;          // emb block of 4 (0..7)
    const int r0   = wrp * 4;

    float mind[4]; int midx[4];
#pragma unroll
    for (int i = 0; i < 4; i++) { mind[i] = 3.0e38f; midx[i] = 0; }

    const float* fbase = sm + OFF_FEAT + r0 * FEAT_STRIDE;

    for (int g = 0; g < 16; g++) {
        const int n = g * 4 + nl;
        const float* wb = Wp + ((size_t)n * EMB + eb * 4) * FEAT;

        u64 acc[4][4];
#pragma unroll
        for (int rr = 0; rr < 4; rr++)
#pragma unroll
            for (int j = 0; j < 4; j++) acc[rr][j] = 0ULL;

#pragma unroll 2
        for (int k = 0; k < FEAT; k += 4) {
            ulonglong2 wq0 = *(const ulonglong2*)(wb + 0 * FEAT + k);
            ulonglong2 wq1 = *(const ulonglong2*)(wb + 1 * FEAT + k);
            ulonglong2 wq2 = *(const ulonglong2*)(wb + 2 * FEAT + k);
            ulonglong2 wq3 = *(const ulonglong2*)(wb + 3 * FEAT + k);
#pragma unroll
            for (int rr = 0; rr < 4; rr++) {
                ulonglong2 xq = *(const ulonglong2*)(fbase + rr * FEAT_STRIDE + k);
                acc[rr][0] = fma2(xq.x, wq0.x, acc[rr][0]);
                acc[rr][0] = fma2(xq.y, wq0.y, acc[rr][0]);
                acc[rr][1] = fma2(xq.x, wq1.x, acc[rr][1]);
                acc[rr][1] = fma2(xq.y, wq1.y, acc[rr][1]);
                acc[rr][2] = fma2(xq.x, wq2.x, acc[rr][2]);
                acc[rr][2] = fma2(xq.y, wq2.y, acc[rr][2]);
                acc[rr][3] = fma2(xq.x, wq3.x, acc[rr][3]);
                acc[rr][3] = fma2(xq.y, wq3.y, acc[rr][3]);
            }
        }

        // epilogue: per-row partial squared distance over this lane's 4 emb dims
        float4 ev = *(const float4*)(sm + OFF_EEMB + n * EMB + eb * 4);
        float ssum[4];
#pragma unroll
        for (int rr = 0; rr < 4; rr++) {
            float f0a, f0b, f1a, f1b, f2a, f2b, f3a, f3b;
            unpack2(acc[rr][0], f0a, f0b);
            unpack2(acc[rr][1], f1a, f1b);
            unpack2(acc[rr][2], f2a, f2b);
            unpack2(acc[rr][3], f3a, f3b);
            float d0 = (f0a + f0b) - ev.x;
            float d1 = (f1a + f1b) - ev.y;
            float d2 = (f2a + f2b) - ev.z;
            float d3 = (f3a + f3b) - ev.w;
            float ss = fmaf(d0, d0, fmaf(d1, d1, fmaf(d2, d2, d3 * d3)));
            ss += __shfl_xor_sync(0xffffffffu, ss, 1);
            ss += __shfl_xor_sync(0xffffffffu, ss, 2);
            ss += __shfl_xor_sync(0xffffffffu, ss, 4);
            ssum[rr] = ss;
        }

        // full distance (exp) at the eb==0 lane of each env
        float coef = sm[OFF_COEF + n];
        float dval[4];
#pragma unroll
        for (int rr = 0; rr < 4; rr++) dval[rr] = expf(ssum[rr] * coef);
        if (eb == 0) {
#pragma unroll
            for (int rr = 0; rr < 4; rr++)
                out[(size_t)B_TOTAL * 66 + (row0 + r0 + rr) * 64 + n] = dval[rr];
        }

        // cross-env argmin reduce to lane 0 (first-min tie-break on smaller n)
        int bn = n;
#pragma unroll
        for (int s = 8; s <= 16; s <<= 1) {
            int n2 = __shfl_xor_sync(0xffffffffu, bn, s);
#pragma unroll
            for (int rr = 0; rr < 4; rr++) {
                float d2 = __shfl_xor_sync(0xffffffffu, dval[rr], s);
                bool take = (d2 < dval[rr]) || (d2 == dval[rr] && n2 < bn);
                if (take) dval[rr] = d2;
            }
            // note: per-rr winner index may differ; track per-rr indices
            // handled below by redoing with per-rr bn — see per-rr loop version
            bn = bn;  // placeholder (replaced by per-rr logic below)
            (void)n2;
        }
        // --- per-rr index-correct reduction (recompute cleanly) ---
        // redo reduction carrying (d, n) per row to avoid shared bn bug
#pragma unroll
        for (int rr = 0; rr < 4; rr++) {
            float d = (eb == 0) ? expf(ssum[rr] * coef) : 3.0e38f;
            int   ni = n;
#pragma unroll
            for (int s = 8; s <= 16; s <<= 1) {
                float d2 = __shfl_xor_sync(0xffffffffu, d, s);
                int   n2 = __shfl_xor_sync(0xffffffffu, ni, s);
                if (d2 < d || (d2 == d && n2 < ni)) { d = d2; ni = n2; }
            }
            if (lane == 0) {
                if (d < mind[rr]) { mind[rr] = d; midx[rr] = ni; }
            }
        }
    }

    // ==== final outputs (per-warp, no sync needed) ====
#pragma unroll 1
    for (int rr = 0; rr < 4; rr++) {
        int m = __shfl_sync(0xffffffffu, midx[rr], 0);
        size_t grow = row0 + r0 + rr;
        // chosen_mean
        out[(size_t)B_TOTAL * 34 + grow * EMB + lane] = sm[OFF_EEMB + m * EMB + lane];
        // chosen_embedding: recompute f2e[r, m] — lane computes emb dim 'lane'
        const float* wrow = Wp + ((size_t)m * EMB + lane) * FEAT;
        const float* frow = fbase + rr * FEAT_STRIDE;
        u64 a = 0ULL;
#pragma unroll 4
        for (int k = 0; k < FEAT; k += 4) {
            ulonglong2 xq = *(const ulonglong2*)(frow + k);
            ulonglong2 wq = *(const ulonglong2*)(wrow + k);
            a = fma2(xq.x, wq.x, a);
            a = fma2(xq.y, wq.y, a);
        }
        float lo, hi; unpack2(a, lo, hi);
        out[grow * EMB + lane] = lo + hi;
    }
    if (lane == 0) {
#pragma unroll
        for (int rr = 0; rr < 4; rr++) {
            size_t grow = row0 + r0 + rr;
            out[(size_t)B_TOTAL * 32 + grow] = mind[rr];
            out[(size_t)B_TOTAL * 33 + grow] = (float)midx[rr];
        }
    }
}

extern "C" void kernel_launch(void* const* d_in, const int* in_sizes, int n_in,
                              void* d_out, int out_size) {
    const float* obs  = (const float*)d_in[0];
    const float* act  = (const float*)d_in[1];
    const float* obs2 = (const float*)d_in[2];
    const float* rew  = (const float*)d_in[3];
    const float* W0   = (const float*)d_in[4];
    const float* b0   = (const float*)d_in[5];
    const float* W1   = (const float*)d_in[6];
    const float* b1   = (const float*)d_in[7];
    const float* W2   = (const float*)d_in[8];
    const float* b2   = (const float*)d_in[9];
    const float* Wp   = (const float*)d_in[10];
    const float* ee   = (const float*)d_in[11];
    const float* sig  = (const float*)d_in[12];
    float* out = (float*)d_out;

    const size_t smem_bytes = (size_t)SMEM_FLOATS * sizeof(float); // 97808
    cudaFuncSetAttribute(udp_encoder_kernel,
                         cudaFuncAttributeMaxDynamicSharedMemorySize, (int)smem_bytes);

    dim3 grid(B_TOTAL / ROWS);   // 2048 blocks
    dim3 block(NTHREADS);
    udp_encoder_kernel<<<grid, block, smem_bytes>>>(
        obs, act, obs2, rew, W0, b0, W1, b1, W2, b2, Wp, ee, sig, out);
}

// round 12
// speedup vs baseline: 3.2188x; 3.2188x over previous
#include <cuda_runtime.h>
#include <math.h>

#define B_TOTAL 65536
#define OBS 64
#define ACTD 16
#define IND 145
#define HID 256
#define FEAT 128
#define NENV 64
#define EMB 32
#define ROWS 64
#define NTHREADS 512

typedef unsigned long long u64;

__device__ __forceinline__ u64 fma2(u64 a, u64 b, u64 c) {
    u64 d; asm("fma.rn.f32x2 %0,%1,%2,%3;" : "=l"(d) : "l"(a), "l"(b), "l"(c)); return d;
}
__device__ __forceinline__ u64 pack2(float x, float y) {
    u64 d; asm("mov.b64 %0,{%1,%2};" : "=l"(d) : "f"(x), "f"(y)); return d;
}
__device__ __forceinline__ void unpack2(u64 v, float& x, float& y) {
    asm("mov.b64 {%0,%1},%2;" : "=f"(x), "=f"(y) : "l"(v));
}

// ---- repacked weights (k-quads): Wq[j][c] = (W[4j][c], W[4j+1][c], W[4j+2][c], W[4j+3][c])
#define KQ0 37   // ceil(145/4), zero-padded
#define KQ1 64
#define KQ2 64
__device__ float4 g_w0q[KQ0 * 256];
__device__ float4 g_w1q[KQ1 * 256];
__device__ float4 g_w2q[KQ2 * 128];

__global__ void repack_kernel(const float* __restrict__ W0,
                              const float* __restrict__ W1,
                              const float* __restrict__ W2) {
    int i = blockIdx.x * 256 + threadIdx.x;
    if (i < KQ0 * 256) {
        int j = i >> 8, c = i & 255;
        float4 v;
        v.x = (4 * j + 0 < IND) ? W0[(4 * j + 0) * 256 + c] : 0.0f;
        v.y = (4 * j + 1 < IND) ? W0[(4 * j + 1) * 256 + c] : 0.0f;
        v.z = (4 * j + 2 < IND) ? W0[(4 * j + 2) * 256 + c] : 0.0f;
        v.w = (4 * j + 3 < IND) ? W0[(4 * j + 3) * 256 + c] : 0.0f;
        g_w0q[i] = v;
    } else if (i < KQ0 * 256 + KQ1 * 256) {
        int idx = i - KQ0 * 256;
        int j = idx >> 8, c = idx & 255;
        g_w1q[idx] = make_float4(W1[(4 * j + 0) * 256 + c], W1[(4 * j + 1) * 256 + c],
                                 W1[(4 * j + 2) * 256 + c], W1[(4 * j + 3) * 256 + c]);
    } else if (i < KQ0 * 256 + KQ1 * 256 + KQ2 * 128) {
        int idx = i - KQ0 * 256 - KQ1 * 256;
        int j = idx >> 7, c = idx & 127;
        g_w2q[idx] = make_float4(W2[(4 * j + 0) * 128 + c], W2[(4 * j + 1) * 128 + c],
                                 W2[(4 * j + 2) * 128 + c], W2[(4 * j + 3) * 128 + c]);
    }
}

// ---- shared memory layout (float offsets), all bases 16B-aligned ----
#define XS 148                 // X row stride (145 -> 148, mult of 4)
#define HS 260                 // H0/H1 row stride (256+4)
#define FS 132                 // feat row stride (128+4)
#define OFF_X     0            // 64*148 = 9472 ; feat (64*132=8448) aliases
#define OFF_FEAT  0
#define OFF_H0    9472         // 64*260 = 16640
#define OFF_H1    26112        // 64*260 = 16640
#define OFF_WT    9472         // projection tile: 128 c * 33 f4 = 16896 floats*4 = aliases H0(+H1 head)
#define OFF_EEMB  42752        // 64*32 = 2048
#define OFF_BEST  44800        // 64*32 = 2048
#define OFF_COEF  46848        // 64
#define SMEM_FLOATS 46912      // 187648 bytes

// Dense layer, row-major in/out, quad-k weights, packed f32x2 FMA, no packs.
// tx = tid&63 -> cols {tx+64j}; ty = tid>>6 -> rows [ty*8, ty*8+8)
template<int NJ, int KQ>
__device__ __forceinline__ void dense_q(
    const float* __restrict__ in_rm, int in_stride,
    const float4* __restrict__ Wq, const float* __restrict__ bias, int C,
    float* __restrict__ out_rm, int out_stride, int tid)
{
    const int tx = tid & 63;
    const int ty = tid >> 6;
    u64 acc[8][NJ];
#pragma unroll
    for (int jj = 0; jj < NJ; jj++) {
        float bb = __ldg(&bias[tx + 64 * jj]);
        u64 b2 = pack2(bb, 0.0f);
#pragma unroll
        for (int r = 0; r < 8; r++) acc[r][jj] = b2;
    }
    const float* xrow = in_rm + (ty * 8) * in_stride;
#pragma unroll 2
    for (int j = 0; j < KQ; j++) {
        ulonglong2 w[NJ];
#pragma unroll
        for (int jj = 0; jj < NJ; jj++)
            w[jj] = *(const ulonglong2*)&Wq[j * C + tx + 64 * jj];
#pragma unroll
        for (int r = 0; r < 8; r++) {
            ulonglong2 xq = *(const ulonglong2*)(xrow + r * in_stride + 4 * j);
#pragma unroll
            for (int jj = 0; jj < NJ; jj++) {
                acc[r][jj] = fma2(xq.x, w[jj].x, acc[r][jj]);
                acc[r][jj] = fma2(xq.y, w[jj].y, acc[r][jj]);
            }
        }
    }
#pragma unroll
    for (int r = 0; r < 8; r++) {
#pragma unroll
        for (int jj = 0; jj < NJ; jj++) {
            float lo, hi; unpack2(acc[r][jj], lo, hi);
            float s = lo + hi;
            out_rm[(ty * 8 + r) * out_stride + tx + 64 * jj] = fmaxf(s, 0.01f * s);
        }
    }
}

extern __shared__ float sm[];

__global__ void __launch_bounds__(NTHREADS, 1)
udp_encoder_kernel(
    const float* __restrict__ obs,  const float* __restrict__ act,
    const float* __restrict__ obs2, const float* __restrict__ rew,
    const float* __restrict__ b0,   const float* __restrict__ b1,
    const float* __restrict__ b2,   const float* __restrict__ Wp,
    const float* __restrict__ ee,   const float* __restrict__ sig,
    float* __restrict__ out)
{
    const int tid = threadIdx.x;
    const size_t row0 = (size_t)blockIdx.x * ROWS;

    // ---- stage e_emb + sigma coefficients ----
    for (int i = tid; i < NENV * EMB; i += NTHREADS) sm[OFF_EEMB + i] = ee[i];
    if (tid < NENV) {
        float s = sig[tid];
        sm[OFF_COEF + tid] = -1.0f / (64.0f * s * s);
    }

    // ---- build row-major input tile X[r][k], stride 148, k=145..147 zero ----
    for (int i = tid; i < ROWS * OBS; i += NTHREADS) {
        int r = i >> 6, k = i & 63;
        float o  = obs [(row0 + r) * OBS + k];
        float o2 = obs2[(row0 + r) * OBS + k];
        sm[OFF_X + r * XS + k]      = o;
        sm[OFF_X + r * XS + 64 + k] = o2 - o;
    }
    for (int i = tid; i < ROWS * ACTD; i += NTHREADS) {
        int r = i >> 4, k = i & 15;
        sm[OFF_X + r * XS + 128 + k] = act[(row0 + r) * ACTD + k];
    }
    if (tid < ROWS) {
        sm[OFF_X + tid * XS + 144] = rew[row0 + tid];
        sm[OFF_X + tid * XS + 145] = 0.0f;
        sm[OFF_X + tid * XS + 146] = 0.0f;
        sm[OFF_X + tid * XS + 147] = 0.0f;
    }
    __syncthreads();

    // ---- MLP ----
    dense_q<4, KQ0>(sm + OFF_X,  XS, g_w0q, b0, 256, sm + OFF_H0,   HS, tid);
    __syncthreads();
    dense_q<4, KQ1>(sm + OFF_H0, HS, g_w1q, b1, 256, sm + OFF_H1,   HS, tid);
    __syncthreads();
    dense_q<2, KQ2>(sm + OFF_H1, HS, g_w2q, b2, 128, sm + OFF_FEAT, FS, tid);
    // (sync happens at top of projection loop)

    // ==== projection + distance + argmin ====
    const int lane = tid & 31;
    const int wrp  = tid >> 5;          // 16 warps x 4 rows
    const int nl   = lane >> 3;         // env within group (0..3)
    const int eb   = lane & 7;          // lane's emb dims: e = eb + 8j
    const int r0   = wrp * 4;

    float mind[4]; int midx[4];         // replicated across lanes
#pragma unroll
    for (int i = 0; i < 4; i++) { mind[i] = 3.0e38f; midx[i] = 0; }

    float4* wt = (float4*)(sm + OFF_WT);          // [c][kq], stride 33 f4
    const float4* WpQ = (const float4*)Wp;        // [n][e][kq] quads, native layout
    const float* fbase = sm + OFF_FEAT + r0 * FS;

    for (int g = 0; g < 16; g++) {
        __syncthreads();   // previous-tile readers (and feat/H0 writers) done
        // stage W tile: warp handles c = wrp + 16*i; lane = kq (coalesced LDG, conflict-free STS)
#pragma unroll
        for (int i = 0; i < 8; i++) {
            int c = wrp + 16 * i;
            int n_l = c >> 5, e = c & 31;
            float4 v = WpQ[((size_t)(g * 4 + n_l) * EMB + e) * 32 + lane];
            wt[c * 33 + lane] = v;
        }
        __syncthreads();

        const int n = g * 4 + nl;
        float eev[4];
#pragma unroll
        for (int j = 0; j < 4; j++) eev[j] = sm[OFF_EEMB + n * EMB + eb + 8 * j];
        float cf = sm[OFF_COEF + n];

        u64 acc[4][4];
#pragma unroll
        for (int r = 0; r < 4; r++)
#pragma unroll
            for (int j = 0; j < 4; j++) acc[r][j] = 0ULL;

#pragma unroll 2
        for (int kq = 0; kq < 32; kq++) {
            ulonglong2 w[4];
#pragma unroll
            for (int j = 0; j < 4; j++)
                w[j] = *(const ulonglong2*)&wt[(nl * 32 + eb + 8 * j) * 33 + kq];
#pragma unroll
            for (int r = 0; r < 4; r++) {
                ulonglong2 xq = *(const ulonglong2*)(fbase + r * FS + 4 * kq);
#pragma unroll
                for (int j = 0; j < 4; j++) {
                    acc[r][j] = fma2(xq.x, w[j].x, acc[r][j]);
                    acc[r][j] = fma2(xq.y, w[j].y, acc[r][j]);
                }
            }
        }

        // epilogue: distances, argmin, winner-copy — all in-warp
#pragma unroll
        for (int r = 0; r < 4; r++) {
            float f[4];
#pragma unroll
            for (int j = 0; j < 4; j++) {
                float lo, hi; unpack2(acc[r][j], lo, hi);
                f[j] = lo + hi;
            }
            float ss = 0.0f;
#pragma unroll
            for (int j = 0; j < 4; j++) {
                float d = f[j] - eev[j];
                ss = fmaf(d, d, ss);
            }
            ss += __shfl_xor_sync(0xffffffffu, ss, 1);
            ss += __shfl_xor_sync(0xffffffffu, ss, 2);
            ss += __shfl_xor_sync(0xffffffffu, ss, 4);
            float dv = expf(ss * cf);
            if (eb == 0)
                out[(size_t)B_TOTAL * 66 + (row0 + r0 + r) * 64 + n] = dv;

            float dred = (eb == 0) ? dv : 3.0e38f;
            int   nred = n;
#pragma unroll
            for (int s = 8; s <= 16; s <<= 1) {
                float d2 = __shfl_xor_sync(0xffffffffu, dred, s);
                int   n2 = __shfl_xor_sync(0xffffffffu, nred, s);
                if (d2 < dred || (d2 == dred && n2 < nred)) { dred = d2; nred = n2; }
            }
            float wd = __shfl_sync(0xffffffffu, dred, 0);
            int   wn = __shfl_sync(0xffffffffu, nred, 0);

            if (wd < mind[r]) {
                mind[r] = wd; midx[r] = wn;
                if (nl == (wn & 3)) {
#pragma unroll
                    for (int j = 0; j < 4; j++)
                        sm[OFF_BEST + (r0 + r) * EMB + eb + 8 * j] = f[j];
                }
            }
        }
    }
    __syncwarp();

    // ==== final outputs (per-warp) ====
#pragma unroll
    for (int r = 0; r < 4; r++) {
        size_t grow = row0 + r0 + r;
        int m = midx[r];
        out[grow * EMB + lane] = sm[OFF_BEST + (r0 + r) * EMB + lane];            // chosen_embedding
        out[(size_t)B_TOTAL * 34 + grow * EMB + lane] = sm[OFF_EEMB + m * EMB + lane]; // chosen_mean
        if (lane == 0) {
            out[(size_t)B_TOTAL * 32 + grow] = mind[r];    // chosen_dist
            out[(size_t)B_TOTAL * 33 + grow] = (float)m;   // idx
        }
    }
}

extern "C" void kernel_launch(void* const* d_in, const int* in_sizes, int n_in,
                              void* d_out, int out_size) {
    const float* obs  = (const float*)d_in[0];
    const float* act  = (const float*)d_in[1];
    const float* obs2 = (const float*)d_in[2];
    const float* rew  = (const float*)d_in[3];
    const float* W0   = (const float*)d_in[4];
    const float* b0   = (const float*)d_in[5];
    const float* W1   = (const float*)d_in[6];
    const float* b1   = (const float*)d_in[7];
    const float* W2   = (const float*)d_in[8];
    const float* b2   = (const float*)d_in[9];
    const float* Wp   = (const float*)d_in[10];
    const float* ee   = (const float*)d_in[11];
    const float* sig  = (const float*)d_in[12];
    float* out = (float*)d_out;

    // repack weights into k-quads (runs every call; deterministic, capturable)
    int total = KQ0 * 256 + KQ1 * 256 + KQ2 * 128;
    repack_kernel<<<(total + 255) / 256, 256>>>(W0, W1, W2);

    const size_t smem_bytes = (size_t)SMEM_FLOATS * sizeof(float); // 187648
    cudaFuncSetAttribute(udp_encoder_kernel,
                         cudaFuncAttributeMaxDynamicSharedMemorySize, (int)smem_bytes);

    dim3 grid(B_TOTAL / ROWS);   // 1024 blocks
    dim3 block(NTHREADS);
    udp_encoder_kernel<<<grid, block, smem_bytes>>>(
        obs, act, obs2, rew, b0, b1, b2, Wp, ee, sig, out);
}

// round 13
// speedup vs baseline: 3.2660x; 1.0147x over previous
#include <cuda_runtime.h>
#include <math.h>

#define B_TOTAL 65536
#define OBS 64
#define ACTD 16
#define IND 145
#define HID 256
#define FEAT 128
#define NENV 64
#define EMB 32
#define ROWS 32
#define NTHREADS 256

typedef unsigned long long u64;

__device__ __forceinline__ u64 fma2(u64 a, u64 b, u64 c) {
    u64 d; asm("fma.rn.f32x2 %0,%1,%2,%3;" : "=l"(d) : "l"(a), "l"(b), "l"(c)); return d;
}
__device__ __forceinline__ u64 pack2(float x, float y) {
    u64 d; asm("mov.b64 %0,{%1,%2};" : "=l"(d) : "f"(x), "f"(y)); return d;
}
__device__ __forceinline__ void unpack2(u64 v, float& x, float& y) {
    asm("mov.b64 {%0,%1},%2;" : "=f"(x), "=f"(y) : "l"(v));
}

// ---- repacked weights (k-quads): Wq[j][c] = (W[4j..4j+3][c])
#define KQ0 37   // ceil(145/4), zero-padded
#define KQ1 64
#define KQ2 64
__device__ float4 g_w0q[KQ0 * 256];
__device__ float4 g_w1q[KQ1 * 256];
__device__ float4 g_w2q[KQ2 * 128];

__global__ void repack_kernel(const float* __restrict__ W0,
                              const float* __restrict__ W1,
                              const float* __restrict__ W2) {
    int i = blockIdx.x * 256 + threadIdx.x;
    if (i < KQ0 * 256) {
        int j = i >> 8, c = i & 255;
        float4 v;
        v.x = (4 * j + 0 < IND) ? W0[(4 * j + 0) * 256 + c] : 0.0f;
        v.y = (4 * j + 1 < IND) ? W0[(4 * j + 1) * 256 + c] : 0.0f;
        v.z = (4 * j + 2 < IND) ? W0[(4 * j + 2) * 256 + c] : 0.0f;
        v.w = (4 * j + 3 < IND) ? W0[(4 * j + 3) * 256 + c] : 0.0f;
        g_w0q[i] = v;
    } else if (i < KQ0 * 256 + KQ1 * 256) {
        int idx = i - KQ0 * 256;
        int j = idx >> 8, c = idx & 255;
        g_w1q[idx] = make_float4(W1[(4 * j + 0) * 256 + c], W1[(4 * j + 1) * 256 + c],
                                 W1[(4 * j + 2) * 256 + c], W1[(4 * j + 3) * 256 + c]);
    } else if (i < KQ0 * 256 + KQ1 * 256 + KQ2 * 128) {
        int idx = i - KQ0 * 256 - KQ1 * 256;
        int j = idx >> 7, c = idx & 127;
        g_w2q[idx] = make_float4(W2[(4 * j + 0) * 128 + c], W2[(4 * j + 1) * 128 + c],
                                 W2[(4 * j + 2) * 128 + c], W2[(4 * j + 3) * 128 + c]);
    }
}

// ---- shared memory layout (float offsets), all bases 16B-aligned ----
#define XS 148                 // X row stride
#define HS 260                 // H0/H1 row stride
#define FS 132                 // feat row stride
#define OFF_X     0            // 32*148 = 4736 ; feat (32*132=4224) aliases
#define OFF_FEAT  0
#define OFF_H0    4736         // 32*260 = 8320
#define OFF_H1    13056        // 32*260 = 8320 -> ends 21376
#define OFF_WT    4736         // proj tile 128c * 33 f4 = 16896 floats -> ends 21632 (H0+H1+slack)
#define OFF_EEMB  21632        // 64*32 = 2048
#define OFF_BEST  23680        // 32*32 = 1024
#define OFF_COEF  24704        // 64
#define SMEM_FLOATS 24768      // 99072 bytes -> 2 CTAs/SM (198144 <= 228KB)

// Dense layer, row-major in/out, quad-k weights, packed f32x2 FMA, no packs.
// tx = tid&63 -> cols {tx+64jj}; ty = tid>>6 (0..3) -> rows [ty*8, ty*8+8)
template<int NJ, int KQ>
__device__ __forceinline__ void dense_q(
    const float* __restrict__ in_rm, int in_stride,
    const float4* __restrict__ Wq, const float* __restrict__ bias, int C,
    float* __restrict__ out_rm, int out_stride, int tid)
{
    const int tx = tid & 63;
    const int ty = tid >> 6;
    u64 acc[8][NJ];
#pragma unroll
    for (int jj = 0; jj < NJ; jj++) {
        float bb = __ldg(&bias[tx + 64 * jj]);
        u64 b2 = pack2(bb, 0.0f);
#pragma unroll
        for (int r = 0; r < 8; r++) acc[r][jj] = b2;
    }
    const float* xrow = in_rm + (ty * 8) * in_stride;
#pragma unroll 2
    for (int j = 0; j < KQ; j++) {
        ulonglong2 w[NJ];
#pragma unroll
        for (int jj = 0; jj < NJ; jj++)
            w[jj] = *(const ulonglong2*)&Wq[j * C + tx + 64 * jj];
#pragma unroll
        for (int r = 0; r < 8; r++) {
            ulonglong2 xq = *(const ulonglong2*)(xrow + r * in_stride + 4 * j);
#pragma unroll
            for (int jj = 0; jj < NJ; jj++) {
                acc[r][jj] = fma2(xq.x, w[jj].x, acc[r][jj]);
                acc[r][jj] = fma2(xq.y, w[jj].y, acc[r][jj]);
            }
        }
    }
#pragma unroll
    for (int r = 0; r < 8; r++) {
#pragma unroll
        for (int jj = 0; jj < NJ; jj++) {
            float lo, hi; unpack2(acc[r][jj], lo, hi);
            float s = lo + hi;
            out_rm[(ty * 8 + r) * out_stride + tx + 64 * jj] = fmaxf(s, 0.01f * s);
        }
    }
}

extern __shared__ float sm[];

__global__ void __launch_bounds__(NTHREADS, 2)
udp_encoder_kernel(
    const float* __restrict__ obs,  const float* __restrict__ act,
    const float* __restrict__ obs2, const float* __restrict__ rew,
    const float* __restrict__ b0,   const float* __restrict__ b1,
    const float* __restrict__ b2,   const float* __restrict__ Wp,
    const float* __restrict__ ee,   const float* __restrict__ sig,
    float* __restrict__ out)
{
    const int tid = threadIdx.x;
    const size_t row0 = (size_t)blockIdx.x * ROWS;

    // ---- stage e_emb + sigma coefficients ----
    for (int i = tid; i < NENV * EMB; i += NTHREADS) sm[OFF_EEMB + i] = ee[i];
    if (tid < NENV) {
        float s = sig[tid];
        sm[OFF_COEF + tid] = -1.0f / (64.0f * s * s);
    }

    // ---- build row-major input tile X[r][k], stride 148, k=145..147 zero ----
    for (int i = tid; i < ROWS * OBS; i += NTHREADS) {
        int r = i >> 6, k = i & 63;
        float o  = obs [(row0 + r) * OBS + k];
        float o2 = obs2[(row0 + r) * OBS + k];
        sm[OFF_X + r * XS + k]      = o;
        sm[OFF_X + r * XS + 64 + k] = o2 - o;
    }
    for (int i = tid; i < ROWS * ACTD; i += NTHREADS) {
        int r = i >> 4, k = i & 15;
        sm[OFF_X + r * XS + 128 + k] = act[(row0 + r) * ACTD + k];
    }
    if (tid < ROWS) {
        sm[OFF_X + tid * XS + 144] = rew[row0 + tid];
        sm[OFF_X + tid * XS + 145] = 0.0f;
        sm[OFF_X + tid * XS + 146] = 0.0f;
        sm[OFF_X + tid * XS + 147] = 0.0f;
    }
    __syncthreads();

    // ---- MLP ----
    dense_q<4, KQ0>(sm + OFF_X,  XS, g_w0q, b0, 256, sm + OFF_H0,   HS, tid);
    __syncthreads();
    dense_q<4, KQ1>(sm + OFF_H0, HS, g_w1q, b1, 256, sm + OFF_H1,   HS, tid);
    __syncthreads();
    dense_q<2, KQ2>(sm + OFF_H1, HS, g_w2q, b2, 128, sm + OFF_FEAT, FS, tid);
    // (sync happens at top of projection loop)

    // ==== projection + distance + argmin ====
    const int lane = tid & 31;
    const int wrp  = tid >> 5;          // 8 warps x 4 rows = 32 rows
    const int nl   = lane >> 3;         // env within group (0..3)
    const int eb   = lane & 7;          // lane's emb dims: e = eb + 8j
    const int r0   = wrp * 4;

    float mind[4]; int midx[4];         // replicated across lanes
#pragma unroll
    for (int i = 0; i < 4; i++) { mind[i] = 3.0e38f; midx[i] = 0; }

    float4* wt = (float4*)(sm + OFF_WT);          // [c][kq], stride 33 f4
    const float4* WpQ = (const float4*)Wp;        // [n][e][kq] quads, native layout
    const float* fbase = sm + OFF_FEAT + r0 * FS;

    for (int g = 0; g < 16; g++) {
        __syncthreads();   // previous-tile readers (and feat/H1 use) done
        // stage W tile: warp handles c = wrp + 8*i (i<16); lane = kq (coalesced LDG, clean STS)
#pragma unroll
        for (int i = 0; i < 16; i++) {
            int c = wrp + 8 * i;
            int n_l = c >> 5, e = c & 31;
            float4 v = WpQ[((size_t)(g * 4 + n_l) * EMB + e) * 32 + lane];
            wt[c * 33 + lane] = v;
        }
        __syncthreads();

        const int n = g * 4 + nl;
        float eev[4];
#pragma unroll
        for (int j = 0; j < 4; j++) eev[j] = sm[OFF_EEMB + n * EMB + eb + 8 * j];
        float cf = sm[OFF_COEF + n];

        u64 acc[4][4];
#pragma unroll
        for (int r = 0; r < 4; r++)
#pragma unroll
            for (int j = 0; j < 4; j++) acc[r][j] = 0ULL;

#pragma unroll 2
        for (int kq = 0; kq < 32; kq++) {
            ulonglong2 w[4];
#pragma unroll
            for (int j = 0; j < 4; j++)
                w[j] = *(const ulonglong2*)&wt[(nl * 32 + eb + 8 * j) * 33 + kq];
#pragma unroll
            for (int r = 0; r < 4; r++) {
                ulonglong2 xq = *(const ulonglong2*)(fbase + r * FS + 4 * kq);
#pragma unroll
                for (int j = 0; j < 4; j++) {
                    acc[r][j] = fma2(xq.x, w[j].x, acc[r][j]);
                    acc[r][j] = fma2(xq.y, w[j].y, acc[r][j]);
                }
            }
        }

        // epilogue: distances, argmin, winner-copy — all in-warp
#pragma unroll
        for (int r = 0; r < 4; r++) {
            float f[4];
#pragma unroll
            for (int j = 0; j < 4; j++) {
                float lo, hi; unpack2(acc[r][j], lo, hi);
                f[j] = lo + hi;
            }
            float ss = 0.0f;
#pragma unroll
            for (int j = 0; j < 4; j++) {
                float d = f[j] - eev[j];
                ss = fmaf(d, d, ss);
            }
            ss += __shfl_xor_sync(0xffffffffu, ss, 1);
            ss += __shfl_xor_sync(0xffffffffu, ss, 2);
            ss += __shfl_xor_sync(0xffffffffu, ss, 4);
            float dv = expf(ss * cf);
            if (eb == 0)
                out[(size_t)B_TOTAL * 66 + (row0 + r0 + r) * 64 + n] = dv;

            float dred = (eb == 0) ? dv : 3.0e38f;
            int   nred = n;
#pragma unroll
            for (int s = 8; s <= 16; s <<= 1) {
                float d2 = __shfl_xor_sync(0xffffffffu, dred, s);
                int   n2 = __shfl_xor_sync(0xffffffffu, nred, s);
                if (d2 < dred || (d2 == dred && n2 < nred)) { dred = d2; nred = n2; }
            }
            float wd = __shfl_sync(0xffffffffu, dred, 0);
            int   wn = __shfl_sync(0xffffffffu, nred, 0);

            if (wd < mind[r]) {
                mind[r] = wd; midx[r] = wn;
                if (nl == (wn & 3)) {
#pragma unroll
                    for (int j = 0; j < 4; j++)
                        sm[OFF_BEST + (r0 + r) * EMB + eb + 8 * j] = f[j];
                }
            }
        }
    }
    __syncwarp();

    // ==== final outputs (per-warp) ====
#pragma unroll
    for (int r = 0; r < 4; r++) {
        size_t grow = row0 + r0 + r;
        int m = midx[r];
        out[grow * EMB + lane] = sm[OFF_BEST + (r0 + r) * EMB + lane];                 // chosen_embedding
        out[(size_t)B_TOTAL * 34 + grow * EMB + lane] = sm[OFF_EEMB + m * EMB + lane]; // chosen_mean
        if (lane == 0) {
            out[(size_t)B_TOTAL * 32 + grow] = mind[r];    // chosen_dist
            out[(size_t)B_TOTAL * 33 + grow] = (float)m;   // idx
        }
    }
}

extern "C" void kernel_launch(void* const* d_in, const int* in_sizes, int n_in,
                              void* d_out, int out_size) {
    const float* obs  = (const float*)d_in[0];
    const float* act  = (const float*)d_in[1];
    const float* obs2 = (const float*)d_in[2];
    const float* rew  = (const float*)d_in[3];
    const float* W0   = (const float*)d_in[4];
    const float* b0   = (const float*)d_in[5];
    const float* W1   = (const float*)d_in[6];
    const float* b1   = (const float*)d_in[7];
    const float* W2   = (const float*)d_in[8];
    const float* b2   = (const float*)d_in[9];
    const float* Wp   = (const float*)d_in[10];
    const float* ee   = (const float*)d_in[11];
    const float* sig  = (const float*)d_in[12];
    float* out = (float*)d_out;

    // repack weights into k-quads (runs every call; deterministic, capturable)
    int total = KQ0 * 256 + KQ1 * 256 + KQ2 * 128;
    repack_kernel<<<(total + 255) / 256, 256>>>(W0, W1, W2);

    const size_t smem_bytes = (size_t)SMEM_FLOATS * sizeof(float); // 99072
    cudaFuncSetAttribute(udp_encoder_kernel,
                         cudaFuncAttributeMaxDynamicSharedMemorySize, (int)smem_bytes);

    dim3 grid(B_TOTAL / ROWS);   // 2048 blocks
    dim3 block(NTHREADS);
    udp_encoder_kernel<<<grid, block, smem_bytes>>>(
        obs, act, obs2, rew, b0, b1, b2, Wp, ee, sig, out);
}

// round 14
// speedup vs baseline: 3.5169x; 1.0768x over previous
#include <cuda_runtime.h>
#include <math.h>

#define B_TOTAL 65536
#define OBS 64
#define ACTD 16
#define IND 145
#define HID 256
#define FEAT 128
#define NENV 64
#define EMB 32
#define ROWS 64
#define NTHREADS 512

typedef unsigned long long u64;

__device__ __forceinline__ u64 fma2(u64 a, u64 b, u64 c) {
    u64 d; asm("fma.rn.f32x2 %0,%1,%2,%3;" : "=l"(d) : "l"(a), "l"(b), "l"(c)); return d;
}
__device__ __forceinline__ u64 pack2(float x, float y) {
    u64 d; asm("mov.b64 %0,{%1,%2};" : "=l"(d) : "f"(x), "f"(y)); return d;
}
__device__ __forceinline__ void unpack2(u64 v, float& x, float& y) {
    asm("mov.b64 {%0,%1},%2;" : "=f"(x), "=f"(y) : "l"(v));
}
__device__ __forceinline__ void bar_half(int h) {
    asm volatile("bar.sync %0, %1;" :: "r"(h + 1), "r"(256) : "memory");
}

// ---- repacked weights (k-quads): Wq[j][c] = (W[4j..4j+3][c])
#define KQ0 37   // ceil(145/4), zero-padded
#define KQ1 64
#define KQ2 64
__device__ float4 g_w0q[KQ0 * 256];
__device__ float4 g_w1q[KQ1 * 256];
__device__ float4 g_w2q[KQ2 * 128];

__global__ void repack_kernel(const float* __restrict__ W0,
                              const float* __restrict__ W1,
                              const float* __restrict__ W2) {
    int i = blockIdx.x * 256 + threadIdx.x;
    if (i < KQ0 * 256) {
        int j = i >> 8, c = i & 255;
        float4 v;
        v.x = (4 * j + 0 < IND) ? W0[(4 * j + 0) * 256 + c] : 0.0f;
        v.y = (4 * j + 1 < IND) ? W0[(4 * j + 1) * 256 + c] : 0.0f;
        v.z = (4 * j + 2 < IND) ? W0[(4 * j + 2) * 256 + c] : 0.0f;
        v.w = (4 * j + 3 < IND) ? W0[(4 * j + 3) * 256 + c] : 0.0f;
        g_w0q[i] = v;
    } else if (i < KQ0 * 256 + KQ1 * 256) {
        int idx = i - KQ0 * 256;
        int j = idx >> 8, c = idx & 255;
        g_w1q[idx] = make_float4(W1[(4 * j + 0) * 256 + c], W1[(4 * j + 1) * 256 + c],
                                 W1[(4 * j + 2) * 256 + c], W1[(4 * j + 3) * 256 + c]);
    } else if (i < KQ0 * 256 + KQ1 * 256 + KQ2 * 128) {
        int idx = i - KQ0 * 256 - KQ1 * 256;
        int j = idx >> 7, c = idx & 127;
        g_w2q[idx] = make_float4(W2[(4 * j + 0) * 128 + c], W2[(4 * j + 1) * 128 + c],
                                 W2[(4 * j + 2) * 128 + c], W2[(4 * j + 3) * 128 + c]);
    }
}

// ---- shared memory layout (float offsets), all bases 16B-aligned ----
#define XS 148
#define HS 260
#define FS 132
#define OFF_X     0            // 64*148 = 9472 ; feat (64*132=8448) aliases
#define OFF_FEAT  0
#define OFF_H0    9472         // 64*260 = 16640 -> 26112
#define OFF_H1    26112        // -> 42752
#define OFF_TA    9472         // W tile half A: 128c*33f4 = 16896 fl -> 26368 (over H0+)
#define OFF_TB    26368        // W tile half B -> 43264 (over H1+)
#define OFF_EEMB  43264        // 2048 -> 45312
#define OFF_BESTA 45312        // 2048 -> 47360
#define OFF_BESTB 47360        // 2048 -> 49408
#define OFF_MINA  49408        // 64
#define OFF_MINB  49472        // 64
#define OFF_IDXA  49536        // 64 ints
#define OFF_IDXB  49600        // 64 ints
#define OFF_COEF  49664        // 64
#define SMEM_FLOATS 49728      // 198912 bytes, 1 CTA/SM

// Dense layer, row-major in/out, quad-k weights, packed f32x2 FMA.
// tx = tid&63 -> cols {tx+64jj}; ty = tid>>6 (0..7) -> rows [ty*8, ty*8+8)
template<int NJ, int KQ>
__device__ __forceinline__ void dense_q(
    const float* __restrict__ in_rm, int in_stride,
    const float4* __restrict__ Wq, const float* __restrict__ bias, int C,
    float* __restrict__ out_rm, int out_stride, int tid)
{
    const int tx = tid & 63;
    const int ty = tid >> 6;
    u64 acc[8][NJ];
#pragma unroll
    for (int jj = 0; jj < NJ; jj++) {
        float bb = __ldg(&bias[tx + 64 * jj]);
        u64 b2 = pack2(bb, 0.0f);
#pragma unroll
        for (int r = 0; r < 8; r++) acc[r][jj] = b2;
    }
    const float* xrow = in_rm + (ty * 8) * in_stride;
#pragma unroll 2
    for (int j = 0; j < KQ; j++) {
        ulonglong2 w[NJ];
#pragma unroll
        for (int jj = 0; jj < NJ; jj++)
            w[jj] = *(const ulonglong2*)&Wq[j * C + tx + 64 * jj];
#pragma unroll
        for (int r = 0; r < 8; r++) {
            ulonglong2 xq = *(const ulonglong2*)(xrow + r * in_stride + 4 * j);
#pragma unroll
            for (int jj = 0; jj < NJ; jj++) {
                acc[r][jj] = fma2(xq.x, w[jj].x, acc[r][jj]);
                acc[r][jj] = fma2(xq.y, w[jj].y, acc[r][jj]);
            }
        }
    }
#pragma unroll
    for (int r = 0; r < 8; r++) {
#pragma unroll
        for (int jj = 0; jj < NJ; jj++) {
            float lo, hi; unpack2(acc[r][jj], lo, hi);
            float s = lo + hi;
            out_rm[(ty * 8 + r) * out_stride + tx + 64 * jj] = fmaxf(s, 0.01f * s);
        }
    }
}

extern __shared__ float sm[];

__global__ void __launch_bounds__(NTHREADS, 1)
udp_encoder_kernel(
    const float* __restrict__ obs,  const float* __restrict__ act,
    const float* __restrict__ obs2, const float* __restrict__ rew,
    const float* __restrict__ b0,   const float* __restrict__ b1,
    const float* __restrict__ b2,   const float* __restrict__ Wp,
    const float* __restrict__ ee,   const float* __restrict__ sig,
    float* __restrict__ out)
{
    const int tid = threadIdx.x;
    const size_t row0 = (size_t)blockIdx.x * ROWS;

    // ---- stage e_emb + sigma coefficients ----
    for (int i = tid; i < NENV * EMB; i += NTHREADS) sm[OFF_EEMB + i] = ee[i];
    if (tid < NENV) {
        float s = sig[tid];
        sm[OFF_COEF + tid] = -1.0f / (64.0f * s * s);
    }

    // ---- build row-major input tile X[r][k], stride 148, k=145..147 zero ----
    for (int i = tid; i < ROWS * OBS; i += NTHREADS) {
        int r = i >> 6, k = i & 63;
        float o  = obs [(row0 + r) * OBS + k];
        float o2 = obs2[(row0 + r) * OBS + k];
        sm[OFF_X + r * XS + k]      = o;
        sm[OFF_X + r * XS + 64 + k] = o2 - o;
    }
    for (int i = tid; i < ROWS * ACTD; i += NTHREADS) {
        int r = i >> 4, k = i & 15;
        sm[OFF_X + r * XS + 128 + k] = act[(row0 + r) * ACTD + k];
    }
    if (tid < ROWS) {
        sm[OFF_X + tid * XS + 144] = rew[row0 + tid];
        sm[OFF_X + tid * XS + 145] = 0.0f;
        sm[OFF_X + tid * XS + 146] = 0.0f;
        sm[OFF_X + tid * XS + 147] = 0.0f;
    }
    __syncthreads();

    // ---- MLP ----
    dense_q<4, KQ0>(sm + OFF_X,  XS, g_w0q, b0, 256, sm + OFF_H0,   HS, tid);
    __syncthreads();
    dense_q<4, KQ1>(sm + OFF_H0, HS, g_w1q, b1, 256, sm + OFF_H1,   HS, tid);
    __syncthreads();
    dense_q<2, KQ2>(sm + OFF_H1, HS, g_w2q, b2, 128, sm + OFF_FEAT, FS, tid);
    __syncthreads();   // H0/H1 now dead; feat final

    // ==== projection: two independent halves over env-groups ====
    const int lane = tid & 31;
    const int wrp  = tid >> 5;          // 16 warps
    const int h    = wrp >> 3;          // half 0: g 0..7 ; half 1: g 8..15
    const int wr   = wrp & 7;           // row-warp within half, 8 rows each
    const int nl   = lane >> 3;         // env within group (0..3)
    const int eb   = lane & 7;          // lane's emb dims: e = eb + 8j
    const int r0   = wr * 8;

    float mind[8]; int midx[8];         // replicated across lanes of warp
#pragma unroll
    for (int i = 0; i < 8; i++) { mind[i] = 3.0e38f; midx[i] = 0; }

    float4* wt = (float4*)(sm + (h ? OFF_TB : OFF_TA));   // [c][kq], stride 33 f4
    float*  bestH = sm + (h ? OFF_BESTB : OFF_BESTA);
    const float4* WpQ = (const float4*)Wp;                // [n][e][kq]
    const float* fbase = sm + OFF_FEAT + r0 * FS;

    for (int gg = 0; gg < 8; gg++) {
        const int g = h * 8 + gg;
        bar_half(h);   // previous tile's readers in this half done
        // stage W tile: warp wr covers c = wr + 8*i; lane = kq (coalesced LDG, clean STS)
#pragma unroll
        for (int i = 0; i < 16; i++) {
            int c = wr + 8 * i;
            int n_l = c >> 5, e = c & 31;
            float4 v = WpQ[((size_t)(g * 4 + n_l) * EMB + e) * 32 + lane];
            wt[c * 33 + lane] = v;
        }
        bar_half(h);

        const int n = g * 4 + nl;
        float eev[4];
#pragma unroll
        for (int j = 0; j < 4; j++) eev[j] = sm[OFF_EEMB + n * EMB + eb + 8 * j];
        float cf = sm[OFF_COEF + n];

        u64 acc[8][4];
#pragma unroll
        for (int r = 0; r < 8; r++)
#pragma unroll
            for (int j = 0; j < 4; j++) acc[r][j] = 0ULL;

#pragma unroll 2
        for (int kq = 0; kq < 32; kq++) {
            ulonglong2 w[4];
#pragma unroll
            for (int j = 0; j < 4; j++)
                w[j] = *(const ulonglong2*)&wt[(nl * 32 + eb + 8 * j) * 33 + kq];
#pragma unroll
            for (int r = 0; r < 8; r++) {
                ulonglong2 xq = *(const ulonglong2*)(fbase + r * FS + 4 * kq);
#pragma unroll
                for (int j = 0; j < 4; j++) {
                    acc[r][j] = fma2(xq.x, w[j].x, acc[r][j]);
                    acc[r][j] = fma2(xq.y, w[j].y, acc[r][j]);
                }
            }
        }

        // epilogue: distances, argmin, winner-copy — all in-warp
#pragma unroll
        for (int r = 0; r < 8; r++) {
            float f[4];
#pragma unroll
            for (int j = 0; j < 4; j++) {
                float lo, hi; unpack2(acc[r][j], lo, hi);
                f[j] = lo + hi;
            }
            float ss = 0.0f;
#pragma unroll
            for (int j = 0; j < 4; j++) {
                float d = f[j] - eev[j];
                ss = fmaf(d, d, ss);
            }
            ss += __shfl_xor_sync(0xffffffffu, ss, 1);
            ss += __shfl_xor_sync(0xffffffffu, ss, 2);
            ss += __shfl_xor_sync(0xffffffffu, ss, 4);
            float dv = expf(ss * cf);
            if (eb == 0)
                out[(size_t)B_TOTAL * 66 + (row0 + r0 + r) * 64 + n] = dv;

            float dred = (eb == 0) ? dv : 3.0e38f;
            int   nred = n;
#pragma unroll
            for (int s = 8; s <= 16; s <<= 1) {
                float d2 = __shfl_xor_sync(0xffffffffu, dred, s);
                int   n2 = __shfl_xor_sync(0xffffffffu, nred, s);
                if (d2 < dred || (d2 == dred && n2 < nred)) { dred = d2; nred = n2; }
            }
            float wd = __shfl_sync(0xffffffffu, dred, 0);
            int   wn = __shfl_sync(0xffffffffu, nred, 0);

            if (wd < mind[r]) {
                mind[r] = wd; midx[r] = wn;
                if (nl == (wn & 3)) {
#pragma unroll
                    for (int j = 0; j < 4; j++)
                        bestH[(r0 + r) * EMB + eb + 8 * j] = f[j];
                }
            }
        }
    }

    // publish per-half argmin state
    if (lane == 0) {
        float* minH = sm + (h ? OFF_MINB : OFF_MINA);
        int*   idxH = (int*)sm + (h ? OFF_IDXB : OFF_IDXA);
#pragma unroll
        for (int r = 0; r < 8; r++) {
            minH[r0 + r] = mind[r];
            idxH[r0 + r] = midx[r];
        }
    }
    __syncthreads();

    // ==== combine halves + final outputs: each warp handles 4 rows ====
#pragma unroll
    for (int r = 0; r < 4; r++) {
        int row = wrp * 4 + r;
        size_t grow = row0 + row;
        float da = sm[OFF_MINA + row], db = sm[OFF_MINB + row];
        bool bwin = db < da;   // half A owns smaller n -> wins ties
        float d = bwin ? db : da;
        int m = bwin ? ((int*)sm)[OFF_IDXB + row] : ((int*)sm)[OFF_IDXA + row];
        float e = bwin ? sm[OFF_BESTB + row * EMB + lane]
                       : sm[OFF_BESTA + row * EMB + lane];
        out[grow * EMB + lane] = e;                                             // chosen_embedding
        out[(size_t)B_TOTAL * 34 + grow * EMB + lane] = sm[OFF_EEMB + m * EMB + lane]; // chosen_mean
        if (lane == 0) {
            out[(size_t)B_TOTAL * 32 + grow] = d;          // chosen_dist
            out[(size_t)B_TOTAL * 33 + grow] = (float)m;   // idx
        }
    }
}

extern "C" void kernel_launch(void* const* d_in, const int* in_sizes, int n_in,
                              void* d_out, int out_size) {
    const float* obs  = (const float*)d_in[0];
    const float* act  = (const float*)d_in[1];
    const float* obs2 = (const float*)d_in[2];
    const float* rew  = (const float*)d_in[3];
    const float* W0   = (const float*)d_in[4];
    const float* b0   = (const float*)d_in[5];
    const float* W1   = (const float*)d_in[6];
    const float* b1   = (const float*)d_in[7];
    const float* W2   = (const float*)d_in[8];
    const float* b2   = (const float*)d_in[9];
    const float* Wp   = (const float*)d_in[10];
    const float* ee   = (const float*)d_in[11];
    const float* sig  = (const float*)d_in[12];
    float* out = (float*)d_out;

    int total = KQ0 * 256 + KQ1 * 256 + KQ2 * 128;
    repack_kernel<<<(total + 255) / 256, 256>>>(W0, W1, W2);

    const size_t smem_bytes = (size_t)SMEM_FLOATS * sizeof(float); // 198912
    cudaFuncSetAttribute(udp_encoder_kernel,
                         cudaFuncAttributeMaxDynamicSharedMemorySize, (int)smem_bytes);

    dim3 grid(B_TOTAL / ROWS);   // 1024 blocks
    dim3 block(NTHREADS);
    udp_encoder_kernel<<<grid, block, smem_bytes>>>(
        obs, act, obs2, rew, b0, b1, b2, Wp, ee, sig, out);
}